// round 15
// baseline (speedup 1.0000x reference)
#include <cuda_runtime.h>
#include <cuda_bf16.h>
#include <cuda_fp16.h>
#include <cstddef>
#include <cstdint>

#define NN 50000
#define EE 800000
#define NTILES_MAX 391

// ---------------------------------------------------------------------------
// Device-global scratch
// ---------------------------------------------------------------------------
__device__ float g_bufA[(size_t)NN * 256];   // h1/hg as __half
__device__ float g_bufB[(size_t)NN * 256];   // r1 as __half
__device__ float g_bufC[(size_t)NN * 256];   // gather256 out as __half
__device__ float g_b64A[(size_t)NN * 64];    // gat out as __half; h4 as __half
__device__ float g_b64B[(size_t)NN * 64];    // r2 as __half
__device__ float g_b64C[(size_t)NN * 64];
__device__ float g_b16A[(size_t)NN * 16];    // h3 as __half
__device__ float g_b16B[(size_t)NN * 16];
__device__ float g_b16C[(size_t)NN * 16];
__device__ float g_als[(size_t)NN * 4];
__device__ float g_ald[(size_t)NN * 4];
__device__ float g_dinv[NN];
__device__ int   g_deg[NN];
__device__ int   g_cur[NN];
__device__ int   g_rowptr[NN + 1];
__device__ int   g_csr[EE];
__device__ int   g_bsum[256];
__device__ int   g_boff[256];
__device__ float g_s1[256], g_q1[256];
__device__ float g_s2[64],  g_q2[64];
__device__ float g_s3[16],  g_q3[16];
__device__ int   g_is64;

__device__ uint4 g_iAh[(size_t)NTILES_MAX * 8 * 512];
__device__ uint4 g_iAl[(size_t)NTILES_MAX * 8 * 512];
__device__ uint4 g_iW1h[8192], g_iW1l[8192];
__device__ uint4 g_iR1h[8192], g_iR1l[8192];
__device__ uint4 g_iWgh[8192], g_iWgl[8192];
__device__ uint4 g_iR2h[8192], g_iR2l[8192];

__device__ __forceinline__ float lk01(float x) { return x > 0.f ? x : 0.01f * x; }
__device__ __forceinline__ float lk2 (float x) { return x > 0.f ? x : 0.2f  * x; }

__device__ __forceinline__ int edge_src(const void* ei, int E, int e) {
    if (g_is64) return (int)((const long long*)ei)[e];
    return ((const int*)ei)[e];
}
__device__ __forceinline__ int edge_dst(const void* ei, int E, int e) {
    if (g_is64) return (int)((const long long*)ei)[(size_t)E + e];
    return ((const int*)ei)[(size_t)E + e];
}

// ---------------------------------------------------------------------------
// Graph preprocessing (k_zero now also runs edge dtype detection in block 0)
// ---------------------------------------------------------------------------
__global__ void k_zero(int n, const int* __restrict__ ei32, int E) {
    int i = blockIdx.x * blockDim.x + threadIdx.x;
    if (i < n)   { g_deg[i] = 0; g_cur[i] = 0; }
    if (i < 256) { g_s1[i] = 0.f; g_q1[i] = 0.f; }
    if (i < 64)  { g_s2[i] = 0.f; g_q2[i] = 0.f; }
    if (i < 16)  { g_s3[i] = 0.f; g_q3[i] = 0.f; }
    // dtype detection: odd int32 words of an int64 buffer (values < 2^31) are 0
    if (blockIdx.x == 0 && threadIdx.x < 32) {
        int t = threadIdx.x;
        int o = 0;
        for (int j = 0; j < 8; j++) {
            int idx = 2 * (t + j * 32) + 1;
            if (idx < 2 * E) o |= ei32[idx];
        }
#pragma unroll
        for (int off = 16; off >= 1; off >>= 1)
            o |= __shfl_xor_sync(0xffffffffu, o, off);
        if (t == 0) g_is64 = (o == 0) ? 1 : 0;
    }
}

__global__ void k_count(const void* __restrict__ ei, int E, int n) {
    int e = blockIdx.x * blockDim.x + threadIdx.x;
    if (e >= E) return;
    int d = edge_dst(ei, E, e);
    if ((unsigned)d < (unsigned)n) atomicAdd(&g_deg[d], 1);
}

__global__ void k_psum(int n) {
    __shared__ int sh[256];
    int t = threadIdx.x;
    int i = blockIdx.x * 256 + t;
    int d = (i < n) ? g_deg[i] : 0;
    if (i < n) g_dinv[i] = rsqrtf((float)d + 1.0f);
    sh[t] = d;
    __syncthreads();
#pragma unroll
    for (int off = 128; off > 0; off >>= 1) {
        if (t < off) sh[t] += sh[t + off];
        __syncthreads();
    }
    if (t == 0) g_bsum[blockIdx.x] = sh[0];
}

__global__ void k_bscan(int nb) {
    __shared__ int sh[256];
    int t = threadIdx.x;
    int v = (t < nb) ? g_bsum[t] : 0;
    sh[t] = v;
    __syncthreads();
#pragma unroll
    for (int off = 1; off < 256; off <<= 1) {
        int u = (t >= off) ? sh[t - off] : 0;
        __syncthreads();
        sh[t] += u;
        __syncthreads();
    }
    g_boff[t] = sh[t] - v;
}

__global__ void k_rowptr(int n) {
    __shared__ int sh[256];
    int t = threadIdx.x;
    int i = blockIdx.x * 256 + t;
    int d = (i < n) ? g_deg[i] : 0;
    sh[t] = d;
    __syncthreads();
#pragma unroll
    for (int off = 1; off < 256; off <<= 1) {
        int u = (t >= off) ? sh[t - off] : 0;
        __syncthreads();
        sh[t] += u;
        __syncthreads();
    }
    int excl = sh[t] - d + g_boff[blockIdx.x];
    if (i <= n) g_rowptr[i] = excl;
}

__global__ void k_fill(const void* __restrict__ ei, int E, int n) {
    int e = blockIdx.x * blockDim.x + threadIdx.x;
    if (e >= E) return;
    int src = edge_src(ei, E, e);
    int dst = edge_dst(ei, E, e);
    if ((unsigned)src >= (unsigned)n || (unsigned)dst >= (unsigned)n) return;
    int pos = g_rowptr[dst] + atomicAdd(&g_cur[dst], 1);
    if ((unsigned)pos < (unsigned)EE) g_csr[pos] = src;
}

// ---------------------------------------------------------------------------
// bf16 hi/lo split into fragment-image layout
// ---------------------------------------------------------------------------
__device__ __forceinline__ void bsplit(float v, uint32_t& h, uint32_t& l) {
    __nv_bfloat16 hb = __float2bfloat16(v);
    __nv_bfloat16 lb = __float2bfloat16(v - __bfloat162float(hb));
    h = (uint32_t)__bfloat16_as_ushort(hb);
    l = (uint32_t)__bfloat16_as_ushort(lb);
}

__device__ __forceinline__ void img_store(uint4* ih, uint4* il, int r, int k0,
                                          const float* v)
{
    uint32_t hw[4], lw[4];
#pragma unroll
    for (int j = 0; j < 4; j++) {
        uint32_t h0, l0, h1, l1;
        bsplit(v[2 * j], h0, l0);
        bsplit(v[2 * j + 1], h1, l1);
        hw[j] = h0 | (h1 << 16);
        lw[j] = l0 | (l1 << 16);
    }
    int tile = r >> 7, rr = r & 127;
    int chunk = k0 >> 5;
    int kt = (k0 >> 4) & 1;
    int mt8 = rr >> 4;
    int reg = (((rr & 15) >= 8) ? 1 : 0) + (((k0 & 15) >= 8) ? 2 : 0);
    int u4 = (tile * 8 + chunk) * 512 + ((kt * 8 + mt8) * 4 + reg) * 8 + (rr & 7);
    ih[u4] = make_uint4(hw[0], hw[1], hw[2], hw[3]);
    il[u4] = make_uint4(lw[0], lw[1], lw[2], lw[3]);
}

__global__ void k_splitA(const float* __restrict__ src, uint4* __restrict__ ih,
                         uint4* __restrict__ il, int M, int ntiles)
{
    int task = blockIdx.x * blockDim.x + threadIdx.x;
    int total = ntiles * 128 * 32;
    if (task >= total) return;
    int r = task >> 5, k0 = (task & 31) * 8;
    float v[8];
    if (r < M) {
        const float4* p = (const float4*)(src + (size_t)r * 256 + k0);
        float4 f0 = p[0], f1 = p[1];
        v[0] = f0.x; v[1] = f0.y; v[2] = f0.z; v[3] = f0.w;
        v[4] = f1.x; v[5] = f1.y; v[6] = f1.z; v[7] = f1.w;
    } else {
#pragma unroll
        for (int j = 0; j < 8; j++) v[j] = 0.f;
    }
    img_store(ih, il, r, k0, v);
}

__device__ __forceinline__ void unpack8(uint4 raw, float* f) {
    __half2* hp = (__half2*)&raw;
#pragma unroll
    for (int j = 0; j < 4; j++) {
        float2 p = __half22float2(hp[j]);
        f[2 * j] = p.x;
        f[2 * j + 1] = p.y;
    }
}

__device__ __forceinline__ uint4 pack8(const float* f) {
    uint4 r;
    __half2* hp = (__half2*)&r;
    hp[0] = __floats2half2_rn(f[0], f[1]);
    hp[1] = __floats2half2_rn(f[2], f[3]);
    hp[2] = __floats2half2_rn(f[4], f[5]);
    hp[3] = __floats2half2_rn(f[6], f[7]);
    return r;
}

__device__ __forceinline__ void bn_coef(const float* gs, const float* gq,
                                        const float* g, const float* be,
                                        float invn, int c, float& sc, float& sh)
{
    float mu = gs[c] * invn;
    float var = gq[c] * invn - mu * mu;
    sc = g[c] * rsqrtf(var + 1e-5f);
    sh = be[c] - mu * sc;
}

// fused: x2 = lk01(bn(bnin_fp16)) + res(fp16) -> bf16 hi/lo images (BN coef inline)
__global__ void k_apply_split(const __half* __restrict__ bnin, const __half* __restrict__ res,
                              uint4* __restrict__ ih, uint4* __restrict__ il,
                              const float* __restrict__ g, const float* __restrict__ be,
                              float invn, int M, int ntiles)
{
    int task = blockIdx.x * blockDim.x + threadIdx.x;
    int total = ntiles * 128 * 32;
    if (task >= total) return;
    int r = task >> 5, k0 = (task & 31) * 8;
    float v[8];
    if (r < M) {
        float cv[8], rv[8];
        unpack8(*(const uint4*)(bnin + (size_t)r * 256 + k0), cv);
        unpack8(*(const uint4*)(res  + (size_t)r * 256 + k0), rv);
#pragma unroll
        for (int j = 0; j < 8; j++) {
            float sc, sh;
            bn_coef(g_s1, g_q1, g, be, invn, k0 + j, sc, sh);
            v[j] = lk01(cv[j] * sc + sh) + rv[j];
        }
    } else {
#pragma unroll
        for (int j = 0; j < 8; j++) v[j] = 0.f;
    }
    img_store(ih, il, r, k0, v);
}

__global__ void k_splitB(const float* __restrict__ B, uint32_t* __restrict__ ih,
                         uint32_t* __restrict__ il, int Nc, int nct)
{
    int idx = blockIdx.x * blockDim.x + threadIdx.x;
    int total = nct * 8 * 2048;
    if (idx >= total) return;
    int ctile = idx / (8 * 2048);
    int rem0 = idx % (8 * 2048);
    int chunk = rem0 >> 11;
    int rem = rem0 & 2047;
    int lane = rem & 31;
    int t2 = rem >> 5;
    int reg = t2 & 1;
    int t3 = t2 >> 1;
    int nt16 = t3 & 15;
    int kt = t3 >> 4;
    int n = ctile * 128 + nt16 * 8 + (lane >> 2);
    int k = chunk * 32 + kt * 16 + reg * 8 + (lane & 3) * 2;
    float v0 = (n < Nc) ? B[(size_t)k * Nc + n] : 0.f;
    float v1 = (n < Nc) ? B[(size_t)(k + 1) * Nc + n] : 0.f;
    uint32_t h0, l0, h1, l1;
    bsplit(v0, h0, l0);
    bsplit(v1, h1, l1);
    ih[idx] = h0 | (h1 << 16);
    il[idx] = l0 | (l1 << 16);
}

// ---------------------------------------------------------------------------
// bf16 3-term tensor GEMM from fragment images.
// ---------------------------------------------------------------------------
__device__ __forceinline__ void mma_bf16(float* c, const uint32_t* a, const uint32_t* b) {
    asm volatile(
        "mma.sync.aligned.m16n8k16.row.col.f32.bf16.bf16.f32 "
        "{%0,%1,%2,%3}, {%4,%5,%6,%7}, {%8,%9}, {%0,%1,%2,%3};"
        : "+f"(c[0]), "+f"(c[1]), "+f"(c[2]), "+f"(c[3])
        : "r"(a[0]), "r"(a[1]), "r"(a[2]), "r"(a[3]), "r"(b[0]), "r"(b[1]));
}

__global__ void __launch_bounds__(256) k_gemm_bf16(
    const uint4* __restrict__ iAh, const uint4* __restrict__ iAl,
    const uint4* __restrict__ iBh, const uint4* __restrict__ iBl,
    const float* __restrict__ bias, float* __restrict__ C,
    int M, int Nc, int half_out)
{
    extern __shared__ uint32_t smem[];
    uint32_t sbase;
    asm("{ .reg .u64 t; cvta.to.shared.u64 t, %1; cvt.u32.u64 %0, t; }"
        : "=r"(sbase) : "l"(smem));

    int tid = threadIdx.x, lane = tid & 31, warp = tid >> 5;
    int wm = warp >> 2, wn = warp & 3;
    int tile = blockIdx.y, ctile = blockIdx.x;

    float acc[4][4][4];
#pragma unroll
    for (int mt = 0; mt < 4; mt++)
#pragma unroll
        for (int nt = 0; nt < 4; nt++)
#pragma unroll
            for (int r = 0; r < 4; r++) acc[mt][nt][r] = 0.f;

    auto issue = [&](int ch, int buf) {
        const uint4* s0 = iAh + (size_t)(tile * 8 + ch) * 512;
        const uint4* s1 = iAl + (size_t)(tile * 8 + ch) * 512;
        const uint4* s2 = iBh + (size_t)(ctile * 8 + ch) * 512;
        const uint4* s3 = iBl + (size_t)(ctile * 8 + ch) * 512;
        uint32_t d = sbase + buf * 32768;
#pragma unroll
        for (int i = 0; i < 2; i++) {
            int j = tid + i * 256;
            asm volatile("cp.async.cg.shared.global [%0], [%1], 16;\n"
                         :: "r"(d + j * 16), "l"(s0 + j));
            asm volatile("cp.async.cg.shared.global [%0], [%1], 16;\n"
                         :: "r"(d + 8192 + j * 16), "l"(s1 + j));
            asm volatile("cp.async.cg.shared.global [%0], [%1], 16;\n"
                         :: "r"(d + 16384 + j * 16), "l"(s2 + j));
            asm volatile("cp.async.cg.shared.global [%0], [%1], 16;\n"
                         :: "r"(d + 24576 + j * 16), "l"(s3 + j));
        }
        asm volatile("cp.async.commit_group;\n" ::: "memory");
    };

    issue(0, 0);

    for (int ch = 0; ch < 8; ch++) {
        if (ch + 1 < 8) {
            issue(ch + 1, (ch + 1) & 1);
            asm volatile("cp.async.wait_group 1;\n" ::: "memory");
        } else {
            asm volatile("cp.async.wait_group 0;\n" ::: "memory");
        }
        __syncthreads();

        const uint32_t* Ah = smem + (ch & 1) * 8192;
        const uint32_t* Al = Ah + 2048;
        const uint32_t* Bh = Ah + 4096;
        const uint32_t* Bl = Ah + 6144;

#pragma unroll
        for (int kt = 0; kt < 2; kt++) {
            uint32_t bh[4][2], bl[4][2];
#pragma unroll
            for (int nt = 0; nt < 4; nt++) {
                int base = ((kt * 16 + wn * 4 + nt) * 2) * 32 + lane;
                bh[nt][0] = Bh[base];      bh[nt][1] = Bh[base + 32];
                bl[nt][0] = Bl[base];      bl[nt][1] = Bl[base + 32];
            }
#pragma unroll
            for (int mt = 0; mt < 4; mt++) {
                uint32_t ah[4], al[4];
                int ab = ((kt * 8 + wm * 4 + mt) * 4) * 32 + lane;
                ah[0] = Ah[ab];       ah[1] = Ah[ab + 32];
                ah[2] = Ah[ab + 64];  ah[3] = Ah[ab + 96];
                al[0] = Al[ab];       al[1] = Al[ab + 32];
                al[2] = Al[ab + 64];  al[3] = Al[ab + 96];
#pragma unroll
                for (int nt = 0; nt < 4; nt++) {
                    mma_bf16(acc[mt][nt], ah, bh[nt]);
                    mma_bf16(acc[mt][nt], al, bh[nt]);
                    mma_bf16(acc[mt][nt], ah, bl[nt]);
                }
            }
        }
        __syncthreads();
    }

    int row0 = tile * 128, col0 = ctile * 128;
    int gid = lane >> 2, tig = lane & 3;
    __half* Ch = (__half*)C;
#pragma unroll
    for (int mt = 0; mt < 4; mt++) {
#pragma unroll
        for (int nt = 0; nt < 4; nt++) {
            int col = col0 + wn * 32 + nt * 8 + tig * 2;
            if (col < Nc) {
                float b0 = bias ? bias[col] : 0.f;
                float b1 = bias ? bias[col + 1] : 0.f;
                int r1 = row0 + wm * 64 + mt * 16 + gid;
                int r2 = r1 + 8;
                if (half_out) {
                    if (r1 < M)
                        *(__half2*)(Ch + (size_t)r1 * Nc + col) =
                            __floats2half2_rn(acc[mt][nt][0] + b0, acc[mt][nt][1] + b1);
                    if (r2 < M)
                        *(__half2*)(Ch + (size_t)r2 * Nc + col) =
                            __floats2half2_rn(acc[mt][nt][2] + b0, acc[mt][nt][3] + b1);
                } else {
                    if (r1 < M) {
                        float2 o = make_float2(acc[mt][nt][0] + b0, acc[mt][nt][1] + b1);
                        *(float2*)(C + (size_t)r1 * Nc + col) = o;
                    }
                    if (r2 < M) {
                        float2 o = make_float2(acc[mt][nt][2] + b0, acc[mt][nt][3] + b1);
                        *(float2*)(C + (size_t)r2 * Nc + col) = o;
                    }
                }
            }
        }
    }
}

// ---------------------------------------------------------------------------
// SIMT SGEMM (small layer-3/4 GEMMs); optional fp16 output
// ---------------------------------------------------------------------------
__global__ void __launch_bounds__(256) k_gemm(
    const float* __restrict__ A, const float* __restrict__ B,
    const float* __restrict__ bias, float* __restrict__ C,
    int M, int K, int Nc, int half_out)
{
    __shared__ float As[8][132];
    __shared__ float Bs[8][128];
    int tid = threadIdx.x;
    int tx = tid & 15, ty = tid >> 4;
    int row0 = blockIdx.y * 128, col0 = blockIdx.x * 128;

    int arow = tid >> 1;
    int ak   = (tid & 1) * 4;
    int brow = tid >> 5;
    int bc   = (tid & 31) * 4;

    bool aok = (row0 + arow) < M;
    bool bok = (col0 + bc + 3) < Nc;

    float acc[8][8];
#pragma unroll
    for (int i = 0; i < 8; i++)
#pragma unroll
        for (int j = 0; j < 8; j++) acc[i][j] = 0.f;

    for (int k0 = 0; k0 < K; k0 += 8) {
        float4 av = make_float4(0.f, 0.f, 0.f, 0.f);
        if (aok) av = *(const float4*)(A + (size_t)(row0 + arow) * K + k0 + ak);
        As[ak + 0][arow] = av.x;
        As[ak + 1][arow] = av.y;
        As[ak + 2][arow] = av.z;
        As[ak + 3][arow] = av.w;
        float4 bv = make_float4(0.f, 0.f, 0.f, 0.f);
        if (bok) bv = *(const float4*)(B + (size_t)(k0 + brow) * Nc + col0 + bc);
        *(float4*)&Bs[brow][bc] = bv;
        __syncthreads();
#pragma unroll
        for (int k = 0; k < 8; k++) {
            float4 a0 = *(const float4*)&As[k][ty * 8];
            float4 a1 = *(const float4*)&As[k][ty * 8 + 4];
            float4 b0 = *(const float4*)&Bs[k][tx * 8];
            float4 b1 = *(const float4*)&Bs[k][tx * 8 + 4];
            float a[8] = {a0.x, a0.y, a0.z, a0.w, a1.x, a1.y, a1.z, a1.w};
            float b[8] = {b0.x, b0.y, b0.z, b0.w, b1.x, b1.y, b1.z, b1.w};
#pragma unroll
            for (int i = 0; i < 8; i++)
#pragma unroll
                for (int j = 0; j < 8; j++) acc[i][j] += a[i] * b[j];
        }
        __syncthreads();
    }

    bool cok = (col0 + tx * 8 + 7) < Nc;
    float bvv[8];
#pragma unroll
    for (int j = 0; j < 8; j++)
        bvv[j] = (bias && cok) ? bias[col0 + tx * 8 + j] : 0.f;

    if (cok) {
        __half* Ch = (__half*)C;
#pragma unroll
        for (int i = 0; i < 8; i++) {
            int r = row0 + ty * 8 + i;
            if (r < M) {
                float o[8];
#pragma unroll
                for (int j = 0; j < 8; j++) o[j] = acc[i][j] + bvv[j];
                if (half_out) {
                    *(uint4*)(Ch + (size_t)r * Nc + col0 + tx * 8) = pack8(o);
                } else {
                    float* cp = C + (size_t)r * Nc + col0 + tx * 8;
                    *(float4*)cp = make_float4(o[0], o[1], o[2], o[3]);
                    *(float4*)(cp + 4) = make_float4(o[4], o[5], o[6], o[7]);
                }
            }
        }
    }
}

// ---------------------------------------------------------------------------
// GCN gathers
// ---------------------------------------------------------------------------
__global__ void k_gcn_gather256h(const __half* __restrict__ h, const float* __restrict__ bias,
                                 __half* __restrict__ out, int n)
{
    int gt = blockIdx.x * blockDim.x + threadIdx.x;
    int nd = gt >> 5, lane = gt & 31;
    if (nd >= n) return;
    int f0 = lane * 8;
    float din = g_dinv[nd];
    float sw = din * din;
    float v[8];
    unpack8(*(const uint4*)(h + (size_t)nd * 256 + f0), v);
    const float4* bp = (const float4*)(bias + f0);
    float4 b0 = bp[0], b1 = bp[1];
    float a[8];
    a[0] = v[0] * sw + b0.x; a[1] = v[1] * sw + b0.y;
    a[2] = v[2] * sw + b0.z; a[3] = v[3] * sw + b0.w;
    a[4] = v[4] * sw + b1.x; a[5] = v[5] * sw + b1.y;
    a[6] = v[6] * sw + b1.z; a[7] = v[7] * sw + b1.w;
    int e = g_rowptr[nd], end = g_rowptr[nd + 1];
    for (; e < end; e++) {
        int s = g_csr[e];
        float wg = g_dinv[s] * din;
        float u[8];
        unpack8(*(const uint4*)(h + (size_t)s * 256 + f0), u);
#pragma unroll
        for (int j = 0; j < 8; j++) a[j] += wg * u[j];
    }
    *(uint4*)(out + (size_t)nd * 256 + f0) = pack8(a);
}

// fp16-input gather for C in {16,64}, fp32 output
template <int C>
__global__ void k_gcn_gather_h(const __half* __restrict__ h, const float* __restrict__ bias,
                               float* __restrict__ out, int n)
{
    const int G = C / 4;
    int gt = blockIdx.x * blockDim.x + threadIdx.x;
    int nd = gt / G, sub = gt % G;
    if (nd >= n) return;
    int f0 = sub * 4;
    float din = g_dinv[nd];
    float sw = din * din;
    uint2 raw = *(const uint2*)(h + (size_t)nd * C + f0);
    __half2* hp = (__half2*)&raw;
    float2 v0 = __half22float2(hp[0]);
    float2 v1 = __half22float2(hp[1]);
    float4 b = *(const float4*)(bias + f0);
    float4 a;
    a.x = v0.x * sw + b.x; a.y = v0.y * sw + b.y;
    a.z = v1.x * sw + b.z; a.w = v1.y * sw + b.w;
    int e = g_rowptr[nd], end = g_rowptr[nd + 1];
    for (; e < end; e++) {
        int s = g_csr[e];
        float wg = g_dinv[s] * din;
        uint2 ur = *(const uint2*)(h + (size_t)s * C + f0);
        __half2* up = (__half2*)&ur;
        float2 u0 = __half22float2(up[0]);
        float2 u1 = __half22float2(up[1]);
        a.x += wg * u0.x; a.y += wg * u0.y; a.z += wg * u1.x; a.w += wg * u1.y;
    }
    *(float4*)(out + (size_t)nd * C + f0) = a;
}

// ---------------------------------------------------------------------------
// GAT kernels (fp16 hg input, fp16 output)
// ---------------------------------------------------------------------------
__global__ void k_al(const __half* __restrict__ hg, const float* __restrict__ a_s,
                     const float* __restrict__ a_d, int n)
{
    int gt = blockIdx.x * blockDim.x + threadIdx.x;
    int w = gt >> 5, lane = gt & 31;
    if (w >= n) return;
    float s0 = 0.f, s1 = 0.f, s2 = 0.f, s3 = 0.f;
    float d0 = 0.f, d1 = 0.f, d2 = 0.f, d3 = 0.f;
#pragma unroll
    for (int j = 0; j < 2; j++) {
        int f = lane * 4 + j * 128;
        uint2 raw = *(const uint2*)(hg + (size_t)w * 256 + f);
        __half2* hp = (__half2*)&raw;
        float2 p0 = __half22float2(hp[0]);
        float2 p1 = __half22float2(hp[1]);
        float4 v = make_float4(p0.x, p0.y, p1.x, p1.y);
        float4 as = *(const float4*)(a_s + f);
        float4 ad = *(const float4*)(a_d + f);
        float ps = v.x * as.x + v.y * as.y + v.z * as.z + v.w * as.w;
        float pd = v.x * ad.x + v.y * ad.y + v.z * ad.z + v.w * ad.w;
        bool hi = (lane & 16) != 0;
        if (j == 0) { if (hi) { s1 += ps; d1 += pd; } else { s0 += ps; d0 += pd; } }
        else        { if (hi) { s3 += ps; d3 += pd; } else { s2 += ps; d2 += pd; } }
    }
#pragma unroll
    for (int off = 16; off >= 1; off >>= 1) {
        s0 += __shfl_xor_sync(0xffffffffu, s0, off);
        s1 += __shfl_xor_sync(0xffffffffu, s1, off);
        s2 += __shfl_xor_sync(0xffffffffu, s2, off);
        s3 += __shfl_xor_sync(0xffffffffu, s3, off);
        d0 += __shfl_xor_sync(0xffffffffu, d0, off);
        d1 += __shfl_xor_sync(0xffffffffu, d1, off);
        d2 += __shfl_xor_sync(0xffffffffu, d2, off);
        d3 += __shfl_xor_sync(0xffffffffu, d3, off);
    }
    if (lane == 0) {
        *(float4*)(g_als + 4 * (size_t)w) = make_float4(s0, s1, s2, s3);
        *(float4*)(g_ald + 4 * (size_t)w) = make_float4(d0, d1, d2, d3);
    }
}

__global__ void k_gat(const __half* __restrict__ hg, const float* __restrict__ bg,
                      __half* __restrict__ out, int n)
{
    int gt = blockIdx.x * blockDim.x + threadIdx.x;
    int w = gt >> 5, lane = gt & 31;
    if (w >= n) return;
    float4 ad = *(const float4*)(g_ald + 4 * (size_t)w);
    float4 sf = *(const float4*)(g_als + 4 * (size_t)w);
    float e0 = lk2(sf.x + ad.x), e1 = lk2(sf.y + ad.y);
    float e2 = lk2(sf.z + ad.z), e3 = lk2(sf.w + ad.w);
    float m0 = e0, m1 = e1, m2 = e2, m3 = e3;
    int beg = g_rowptr[w], end = g_rowptr[w + 1];
    for (int e = beg; e < end; e++) {
        int s = g_csr[e];
        float4 a = *(const float4*)(g_als + 4 * (size_t)s);
        m0 = fmaxf(m0, lk2(a.x + ad.x));
        m1 = fmaxf(m1, lk2(a.y + ad.y));
        m2 = fmaxf(m2, lk2(a.z + ad.z));
        m3 = fmaxf(m3, lk2(a.w + ad.w));
    }
    float den0 = __expf(e0 - m0), den1 = __expf(e1 - m1);
    float den2 = __expf(e2 - m2), den3 = __expf(e3 - m3);
    int f0 = lane * 8;
    int head = lane >> 3;
    float wself = head == 0 ? den0 : head == 1 ? den1 : head == 2 ? den2 : den3;
    float v[8];
    unpack8(*(const uint4*)(hg + (size_t)w * 256 + f0), v);
    float a0 = wself * v[0], a1 = wself * v[1], a2 = wself * v[2], a3 = wself * v[3];
    float a4 = wself * v[4], a5 = wself * v[5], a6 = wself * v[6], a7 = wself * v[7];
    for (int e = beg; e < end; e++) {
        int s = g_csr[e];
        float4 a = *(const float4*)(g_als + 4 * (size_t)s);
        float w0 = __expf(lk2(a.x + ad.x) - m0);
        float w1 = __expf(lk2(a.y + ad.y) - m1);
        float w2 = __expf(lk2(a.z + ad.z) - m2);
        float w3 = __expf(lk2(a.w + ad.w) - m3);
        den0 += w0; den1 += w1; den2 += w2; den3 += w3;
        float ws = head == 0 ? w0 : head == 1 ? w1 : head == 2 ? w2 : w3;
        float u[8];
        unpack8(*(const uint4*)(hg + (size_t)s * 256 + f0), u);
        a0 += ws * u[0]; a1 += ws * u[1]; a2 += ws * u[2]; a3 += ws * u[3];
        a4 += ws * u[4]; a5 += ws * u[5]; a6 += ws * u[6]; a7 += ws * u[7];
    }
    float dsel = head == 0 ? den0 : head == 1 ? den1 : head == 2 ? den2 : den3;
    float sc = 0.25f / dsel;
    a0 *= sc; a1 *= sc; a2 *= sc; a3 *= sc;
    a4 *= sc; a5 *= sc; a6 *= sc; a7 *= sc;
    a0 += __shfl_xor_sync(0xffffffffu, a0, 8);  a0 += __shfl_xor_sync(0xffffffffu, a0, 16);
    a1 += __shfl_xor_sync(0xffffffffu, a1, 8);  a1 += __shfl_xor_sync(0xffffffffu, a1, 16);
    a2 += __shfl_xor_sync(0xffffffffu, a2, 8);  a2 += __shfl_xor_sync(0xffffffffu, a2, 16);
    a3 += __shfl_xor_sync(0xffffffffu, a3, 8);  a3 += __shfl_xor_sync(0xffffffffu, a3, 16);
    a4 += __shfl_xor_sync(0xffffffffu, a4, 8);  a4 += __shfl_xor_sync(0xffffffffu, a4, 16);
    a5 += __shfl_xor_sync(0xffffffffu, a5, 8);  a5 += __shfl_xor_sync(0xffffffffu, a5, 16);
    a6 += __shfl_xor_sync(0xffffffffu, a6, 8);  a6 += __shfl_xor_sync(0xffffffffu, a6, 16);
    a7 += __shfl_xor_sync(0xffffffffu, a7, 8);  a7 += __shfl_xor_sync(0xffffffffu, a7, 16);
    if (lane < 8) {
        const float4* bp = (const float4*)(bg + lane * 8);
        float4 b0 = bp[0], b1 = bp[1];
        float o[8] = {a0 + b0.x, a1 + b0.y, a2 + b0.z, a3 + b0.w,
                      a4 + b1.x, a5 + b1.y, a6 + b1.z, a7 + b1.w};
        *(uint4*)(out + (size_t)w * 64 + lane * 8) = pack8(o);
    }
}

// ---------------------------------------------------------------------------
// BatchNorm stats
// ---------------------------------------------------------------------------
template <int C>
__global__ void k_bnstats_h(const __half* __restrict__ x, float* __restrict__ gsum,
                            float* __restrict__ gsq, int n)
{
    __shared__ float ss[256], qq[256];
    int tid = threadIdx.x;
    const int R = 256 / C;
    int c = tid % C, r0 = tid / C;
    float s = 0.f, q = 0.f;
    for (int r = blockIdx.x * R + r0; r < n; r += gridDim.x * R) {
        float v = __half2float(x[(size_t)r * C + c]);
        s += v; q += v * v;
    }
    ss[tid] = s; qq[tid] = q;
    __syncthreads();
#pragma unroll
    for (int off = 128; off >= C; off >>= 1) {
        if (tid < off) { ss[tid] += ss[tid + off]; qq[tid] += qq[tid + off]; }
        __syncthreads();
    }
    if (tid < C) {
        atomicAdd(&gsum[tid], ss[tid]);
        atomicAdd(&gsq[tid],  qq[tid]);
    }
}

template <int C>
__global__ void k_bnstats(const float* __restrict__ x, float* __restrict__ gsum,
                          float* __restrict__ gsq, int n)
{
    __shared__ float ss[256], qq[256];
    int tid = threadIdx.x;
    const int R = 256 / C;
    int c = tid % C, r0 = tid / C;
    float s = 0.f, q = 0.f;
    for (int r = blockIdx.x * R + r0; r < n; r += gridDim.x * R) {
        float v = x[(size_t)r * C + c];
        s += v; q += v * v;
    }
    ss[tid] = s; qq[tid] = q;
    __syncthreads();
#pragma unroll
    for (int off = 128; off >= C; off >>= 1) {
        if (tid < off) { ss[tid] += ss[tid + off]; qq[tid] += qq[tid + off]; }
        __syncthreads();
    }
    if (tid < C) {
        atomicAdd(&gsum[tid], ss[tid]);
        atomicAdd(&gsq[tid],  qq[tid]);
    }
}

// apply C=64, fp16 x + fp16 res -> fp32, BN coef inline (layer 2)
__global__ void k_apply64hh(const __half* __restrict__ x, const __half* __restrict__ res,
                            float* __restrict__ out,
                            const float* __restrict__ g, const float* __restrict__ be,
                            float invn, int n)
{
    int i = blockIdx.x * blockDim.x + threadIdx.x;
    int total = n * 16;
    if (i >= total) return;
    int c0 = (i % 16) * 4;
    uint2 xr = *(const uint2*)(x + (size_t)i * 4);
    uint2 rr = *(const uint2*)(res + (size_t)i * 4);
    __half2* xp = (__half2*)&xr;
    __half2* rp = (__half2*)&rr;
    float2 x0 = __half22float2(xp[0]);
    float2 x1 = __half22float2(xp[1]);
    float2 r0 = __half22float2(rp[0]);
    float2 r1 = __half22float2(rp[1]);
    float xv[4] = {x0.x, x0.y, x1.x, x1.y};
    float rv[4] = {r0.x, r0.y, r1.x, r1.y};
    float4 o;
    float* op = (float*)&o;
#pragma unroll
    for (int j = 0; j < 4; j++) {
        float sc, sh;
        bn_coef(g_s2, g_q2, g, be, invn, c0 + j, sc, sh);
        op[j] = lk01(xv[j] * sc + sh) + rv[j];
    }
    ((float4*)out)[i] = o;
}

// apply C=16, fp32 x + fp32 res -> fp32, BN coef inline (layer 3)
__global__ void k_apply16(const float* __restrict__ x, const float* __restrict__ res,
                          float* __restrict__ out,
                          const float* __restrict__ g, const float* __restrict__ be,
                          float invn, int n)
{
    int i = blockIdx.x * blockDim.x + threadIdx.x;
    int total = n * 4;
    if (i >= total) return;
    int c0 = (i % 4) * 4;
    float4 v = ((const float4*)x)[i];
    float4 r = ((const float4*)res)[i];
    float xv[4] = {v.x, v.y, v.z, v.w};
    float rv[4] = {r.x, r.y, r.z, r.w};
    float4 o;
    float* op = (float*)&o;
#pragma unroll
    for (int j = 0; j < 4; j++) {
        float sc, sh;
        bn_coef(g_s3, g_q3, g, be, invn, c0 + j, sc, sh);
        op[j] = lk01(xv[j] * sc + sh) + rv[j];
    }
    ((float4*)out)[i] = o;
}

// ---------------------------------------------------------------------------
// Launcher
// ---------------------------------------------------------------------------
extern "C" void kernel_launch(void* const* d_in, const int* in_sizes, int n_in,
                              void* d_out, int out_size)
{
    const float* x     = (const float*)d_in[0];
    const void*  ei    = d_in[1];
    const float* W1    = (const float*)d_in[2];
    const float* b1    = (const float*)d_in[3];
    const float* g1    = (const float*)d_in[4];
    const float* be1   = (const float*)d_in[5];
    const float* Wg    = (const float*)d_in[6];
    const float* a_src = (const float*)d_in[7];
    const float* a_dst = (const float*)d_in[8];
    const float* bg    = (const float*)d_in[9];
    const float* g2    = (const float*)d_in[10];
    const float* be2   = (const float*)d_in[11];
    const float* W3    = (const float*)d_in[12];
    const float* b3    = (const float*)d_in[13];
    const float* g3    = (const float*)d_in[14];
    const float* be3   = (const float*)d_in[15];
    const float* W4    = (const float*)d_in[16];
    const float* b4    = (const float*)d_in[17];
    const float* r1W   = (const float*)d_in[18];
    const float* r1b   = (const float*)d_in[19];
    const float* r2W   = (const float*)d_in[20];
    const float* r2b   = (const float*)d_in[21];
    const float* r3W   = (const float*)d_in[22];
    const float* r3b   = (const float*)d_in[23];
    const float* pW    = (const float*)d_in[24];
    const float* pb    = (const float*)d_in[25];

    int n = in_sizes[0] / 256;
    int E = in_sizes[1] / 2;
    if (E > EE) E = EE;
    int ntiles = (n + 127) / 128;
    if (ntiles > NTILES_MAX) ntiles = NTILES_MAX;
    float invn = 1.0f / (float)n;

    float *pA, *pB, *pC, *p64A, *p64B, *p64C, *p16A, *p16B, *p16C;
    float *ps1, *pq1, *ps2, *pq2, *ps3, *pq3;
    uint4 *iAh, *iAl, *iW1h, *iW1l, *iR1h, *iR1l, *iWgh, *iWgl, *iR2h, *iR2l;
    cudaGetSymbolAddress((void**)&pA,   g_bufA);
    cudaGetSymbolAddress((void**)&pB,   g_bufB);
    cudaGetSymbolAddress((void**)&pC,   g_bufC);
    cudaGetSymbolAddress((void**)&p64A, g_b64A);
    cudaGetSymbolAddress((void**)&p64B, g_b64B);
    cudaGetSymbolAddress((void**)&p64C, g_b64C);
    cudaGetSymbolAddress((void**)&p16A, g_b16A);
    cudaGetSymbolAddress((void**)&p16B, g_b16B);
    cudaGetSymbolAddress((void**)&p16C, g_b16C);
    cudaGetSymbolAddress((void**)&ps1, g_s1);
    cudaGetSymbolAddress((void**)&pq1, g_q1);
    cudaGetSymbolAddress((void**)&ps2, g_s2);
    cudaGetSymbolAddress((void**)&pq2, g_q2);
    cudaGetSymbolAddress((void**)&ps3, g_s3);
    cudaGetSymbolAddress((void**)&pq3, g_q3);
    cudaGetSymbolAddress((void**)&iAh,  g_iAh);
    cudaGetSymbolAddress((void**)&iAl,  g_iAl);
    cudaGetSymbolAddress((void**)&iW1h, g_iW1h);
    cudaGetSymbolAddress((void**)&iW1l, g_iW1l);
    cudaGetSymbolAddress((void**)&iR1h, g_iR1h);
    cudaGetSymbolAddress((void**)&iR1l, g_iR1l);
    cudaGetSymbolAddress((void**)&iWgh, g_iWgh);
    cudaGetSymbolAddress((void**)&iWgl, g_iWgl);
    cudaGetSymbolAddress((void**)&iR2h, g_iR2h);
    cudaGetSymbolAddress((void**)&iR2l, g_iR2l);

    float* outp = (float*)d_out;
    const __half* pAh = (const __half*)pA;
    const __half* pBh = (const __half*)pB;
    __half* pCh = (__half*)pC;
    __half* p64Ah = (__half*)p64A;
    const __half* p64Bh = (const __half*)p64B;
    const __half* p16Ah = (const __half*)p16A;

    cudaFuncSetAttribute(k_gemm_bf16, cudaFuncAttributeMaxDynamicSharedMemorySize, 65536);

    int nb = (n + 255) / 256;
    int splitA_blocks = (ntiles * 128 * 32 + 255) / 256;
    dim3 gt256(2, ntiles);
    dim3 gt64 (1, ntiles);
    dim3 gmed (1, ntiles);

    // --- dense front ---
    k_splitB<<<128, 256>>>(W1,  (uint32_t*)iW1h, (uint32_t*)iW1l, 256, 2);
    k_splitB<<<128, 256>>>(r1W, (uint32_t*)iR1h, (uint32_t*)iR1l, 256, 2);
    k_splitB<<<128, 256>>>(Wg,  (uint32_t*)iWgh, (uint32_t*)iWgl, 256, 2);
    k_splitB<<<64,  256>>>(r2W, (uint32_t*)iR2h, (uint32_t*)iR2l, 64, 1);
    k_splitA<<<splitA_blocks, 256>>>(x, iAh, iAl, n, ntiles);
    k_gemm_bf16<<<gt256, 256, 65536>>>(iAh, iAl, iW1h, iW1l, nullptr, pA, n, 256, 1);  // fp16 h1
    k_gemm_bf16<<<gt256, 256, 65536>>>(iAh, iAl, iR1h, iR1l, r1b, pB, n, 256, 1);      // fp16 r1

    // --- graph preprocessing (zero includes dtype detect) ---
    k_zero  <<<nb, 256>>>(n, (const int*)ei, E);
    k_count <<<(E + 255) / 256, 256>>>(ei, E, n);
    k_psum  <<<nb, 256>>>(n);
    k_bscan <<<1, 256>>>(nb);
    k_rowptr<<<nb, 256>>>(n);
    k_fill  <<<(E + 255) / 256, 256>>>(ei, E, n);

    // --- layer 1: gather + BN stats + fused bnfin/apply/split ---
    k_gcn_gather256h<<<(n * 32 + 255) / 256, 256>>>(pAh, b1, pCh, n);
    k_bnstats_h<256><<<512, 256>>>(pCh, ps1, pq1, n);
    k_apply_split<<<splitA_blocks, 256>>>(pCh, pBh, iAh, iAl, g1, be1, invn, n, ntiles);

    // --- layer 2: GAT(256->64) + BN + leaky + residual ---
    k_gemm_bf16<<<gt256, 256, 65536>>>(iAh, iAl, iWgh, iWgl, nullptr, pA, n, 256, 1);  // fp16 hg
    k_gemm_bf16<<<gt64, 256, 65536>>>(iAh, iAl, iR2h, iR2l, r2b, p64B, n, 64, 1);      // fp16 r2
    k_al <<<(n * 32 + 255) / 256, 256>>>(pAh, a_src, a_dst, n);
    k_gat<<<(n * 32 + 255) / 256, 256>>>(pAh, bg, p64Ah, n);
    k_bnstats_h<64><<<512, 256>>>(p64Ah, ps2, pq2, n);
    k_apply64hh<<<(n * 16 + 255) / 256, 256>>>(p64Ah, p64Bh, p64C, g2, be2, invn, n);  // x3 fp32

    // --- layer 3: GCN(64->16) + BN + leaky + residual ---
    k_gemm<<<gmed, 256>>>(p64C, W3, nullptr, p16A, n, 64, 16, 1);                      // fp16 h3
    k_gcn_gather_h<16><<<(n * 4 + 255) / 256, 256>>>(p16Ah, b3, p16B, n);
    k_gemm<<<gmed, 256>>>(p64C, r3W, r3b, p16C, n, 64, 16, 0);
    k_bnstats<16><<<512, 256>>>(p16B, ps3, pq3, n);
    k_apply16<<<(n * 4 + 255) / 256, 256>>>(p16B, p16C, p16A, g3, be3, invn, n);       // x4 fp32

    // --- layer 4: GCN(16->64) + final projection ---
    k_gemm<<<gmed, 256>>>(p16A, W4, nullptr, p64A, n, 16, 64, 1);                      // fp16 h4
    k_gcn_gather_h<64><<<(n * 16 + 255) / 256, 256>>>(p64Ah, b4, p64B, n);
    k_gemm<<<gmed, 256>>>(p64B, pW, pb, outp, n, 64, 64, 0);
}

// round 16
// speedup vs baseline: 1.0616x; 1.0616x over previous
#include <cuda_runtime.h>
#include <cuda_bf16.h>
#include <cuda_fp16.h>
#include <cstddef>
#include <cstdint>

#define NN 50000
#define EE 800000
#define NTILES_MAX 391

// ---------------------------------------------------------------------------
// Device-global scratch
// ---------------------------------------------------------------------------
__device__ float g_bufA[(size_t)NN * 256];   // h1/hg as __half
__device__ float g_bufB[(size_t)NN * 256];   // r1 as __half
__device__ float g_bufC[(size_t)NN * 256];   // gather256 out as __half
__device__ float g_b64A[(size_t)NN * 64];    // gat out as __half; h4 as __half
__device__ float g_b64B[(size_t)NN * 64];    // r2 as __half
__device__ float g_b64C[(size_t)NN * 64];
__device__ float g_b16A[(size_t)NN * 16];    // h3 as __half
__device__ float g_b16B[(size_t)NN * 16];
__device__ float g_b16C[(size_t)NN * 16];
__device__ float g_als[(size_t)NN * 4];
__device__ float g_ald[(size_t)NN * 4];
__device__ float g_dinv[NN];
__device__ int   g_deg[NN];
__device__ int   g_cur[NN];
__device__ int   g_rowptr[NN + 1];
__device__ int   g_csr[EE];
__device__ int   g_bsum[256];
__device__ int   g_boff[256];
__device__ float g_s1[256], g_q1[256];
__device__ float g_s2[64],  g_q2[64];
__device__ float g_s3[16],  g_q3[16];
__device__ float g_scale[256], g_shift[256];
__device__ int   g_is64;

__device__ uint4 g_iAh[(size_t)NTILES_MAX * 8 * 512];
__device__ uint4 g_iAl[(size_t)NTILES_MAX * 8 * 512];
__device__ uint4 g_iW1h[8192], g_iW1l[8192];
__device__ uint4 g_iR1h[8192], g_iR1l[8192];
__device__ uint4 g_iWgh[8192], g_iWgl[8192];
__device__ uint4 g_iR2h[8192], g_iR2l[8192];

__device__ __forceinline__ float lk01(float x) { return x > 0.f ? x : 0.01f * x; }
__device__ __forceinline__ float lk2 (float x) { return x > 0.f ? x : 0.2f  * x; }

__device__ __forceinline__ int edge_src(const void* ei, int E, int e) {
    if (g_is64) return (int)((const long long*)ei)[e];
    return ((const int*)ei)[e];
}
__device__ __forceinline__ int edge_dst(const void* ei, int E, int e) {
    if (g_is64) return (int)((const long long*)ei)[(size_t)E + e];
    return ((const int*)ei)[(size_t)E + e];
}

// ---------------------------------------------------------------------------
// Graph preprocessing (k_zero also runs edge dtype detection in block 0)
// ---------------------------------------------------------------------------
__global__ void k_zero(int n, const int* __restrict__ ei32, int E) {
    int i = blockIdx.x * blockDim.x + threadIdx.x;
    if (i < n)   { g_deg[i] = 0; g_cur[i] = 0; }
    if (i < 256) { g_s1[i] = 0.f; g_q1[i] = 0.f; }
    if (i < 64)  { g_s2[i] = 0.f; g_q2[i] = 0.f; }
    if (i < 16)  { g_s3[i] = 0.f; g_q3[i] = 0.f; }
    if (blockIdx.x == 0 && threadIdx.x < 32) {
        int t = threadIdx.x;
        int o = 0;
        for (int j = 0; j < 8; j++) {
            int idx = 2 * (t + j * 32) + 1;
            if (idx < 2 * E) o |= ei32[idx];
        }
#pragma unroll
        for (int off = 16; off >= 1; off >>= 1)
            o |= __shfl_xor_sync(0xffffffffu, o, off);
        if (t == 0) g_is64 = (o == 0) ? 1 : 0;
    }
}

__global__ void k_count(const void* __restrict__ ei, int E, int n) {
    int e = blockIdx.x * blockDim.x + threadIdx.x;
    if (e >= E) return;
    int d = edge_dst(ei, E, e);
    if ((unsigned)d < (unsigned)n) atomicAdd(&g_deg[d], 1);
}

__global__ void k_psum(int n) {
    __shared__ int sh[256];
    int t = threadIdx.x;
    int i = blockIdx.x * 256 + t;
    int d = (i < n) ? g_deg[i] : 0;
    if (i < n) g_dinv[i] = rsqrtf((float)d + 1.0f);
    sh[t] = d;
    __syncthreads();
#pragma unroll
    for (int off = 128; off > 0; off >>= 1) {
        if (t < off) sh[t] += sh[t + off];
        __syncthreads();
    }
    if (t == 0) g_bsum[blockIdx.x] = sh[0];
}

__global__ void k_bscan(int nb) {
    __shared__ int sh[256];
    int t = threadIdx.x;
    int v = (t < nb) ? g_bsum[t] : 0;
    sh[t] = v;
    __syncthreads();
#pragma unroll
    for (int off = 1; off < 256; off <<= 1) {
        int u = (t >= off) ? sh[t - off] : 0;
        __syncthreads();
        sh[t] += u;
        __syncthreads();
    }
    g_boff[t] = sh[t] - v;
}

__global__ void k_rowptr(int n) {
    __shared__ int sh[256];
    int t = threadIdx.x;
    int i = blockIdx.x * 256 + t;
    int d = (i < n) ? g_deg[i] : 0;
    sh[t] = d;
    __syncthreads();
#pragma unroll
    for (int off = 1; off < 256; off <<= 1) {
        int u = (t >= off) ? sh[t - off] : 0;
        __syncthreads();
        sh[t] += u;
        __syncthreads();
    }
    int excl = sh[t] - d + g_boff[blockIdx.x];
    if (i <= n) g_rowptr[i] = excl;
}

__global__ void k_fill(const void* __restrict__ ei, int E, int n) {
    int e = blockIdx.x * blockDim.x + threadIdx.x;
    if (e >= E) return;
    int src = edge_src(ei, E, e);
    int dst = edge_dst(ei, E, e);
    if ((unsigned)src >= (unsigned)n || (unsigned)dst >= (unsigned)n) return;
    int pos = g_rowptr[dst] + atomicAdd(&g_cur[dst], 1);
    if ((unsigned)pos < (unsigned)EE) g_csr[pos] = src;
}

// ---------------------------------------------------------------------------
// bf16 hi/lo split into fragment-image layout
// ---------------------------------------------------------------------------
__device__ __forceinline__ void bsplit(float v, uint32_t& h, uint32_t& l) {
    __nv_bfloat16 hb = __float2bfloat16(v);
    __nv_bfloat16 lb = __float2bfloat16(v - __bfloat162float(hb));
    h = (uint32_t)__bfloat16_as_ushort(hb);
    l = (uint32_t)__bfloat16_as_ushort(lb);
}

__device__ __forceinline__ void img_store(uint4* ih, uint4* il, int r, int k0,
                                          const float* v)
{
    uint32_t hw[4], lw[4];
#pragma unroll
    for (int j = 0; j < 4; j++) {
        uint32_t h0, l0, h1, l1;
        bsplit(v[2 * j], h0, l0);
        bsplit(v[2 * j + 1], h1, l1);
        hw[j] = h0 | (h1 << 16);
        lw[j] = l0 | (l1 << 16);
    }
    int tile = r >> 7, rr = r & 127;
    int chunk = k0 >> 5;
    int kt = (k0 >> 4) & 1;
    int mt8 = rr >> 4;
    int reg = (((rr & 15) >= 8) ? 1 : 0) + (((k0 & 15) >= 8) ? 2 : 0);
    int u4 = (tile * 8 + chunk) * 512 + ((kt * 8 + mt8) * 4 + reg) * 8 + (rr & 7);
    ih[u4] = make_uint4(hw[0], hw[1], hw[2], hw[3]);
    il[u4] = make_uint4(lw[0], lw[1], lw[2], lw[3]);
}

__global__ void k_splitA(const float* __restrict__ src, uint4* __restrict__ ih,
                         uint4* __restrict__ il, int M, int ntiles)
{
    int task = blockIdx.x * blockDim.x + threadIdx.x;
    int total = ntiles * 128 * 32;
    if (task >= total) return;
    int r = task >> 5, k0 = (task & 31) * 8;
    float v[8];
    if (r < M) {
        const float4* p = (const float4*)(src + (size_t)r * 256 + k0);
        float4 f0 = p[0], f1 = p[1];
        v[0] = f0.x; v[1] = f0.y; v[2] = f0.z; v[3] = f0.w;
        v[4] = f1.x; v[5] = f1.y; v[6] = f1.z; v[7] = f1.w;
    } else {
#pragma unroll
        for (int j = 0; j < 8; j++) v[j] = 0.f;
    }
    img_store(ih, il, r, k0, v);
}

__device__ __forceinline__ void unpack8(uint4 raw, float* f) {
    __half2* hp = (__half2*)&raw;
#pragma unroll
    for (int j = 0; j < 4; j++) {
        float2 p = __half22float2(hp[j]);
        f[2 * j] = p.x;
        f[2 * j + 1] = p.y;
    }
}

__device__ __forceinline__ uint4 pack8(const float* f) {
    uint4 r;
    __half2* hp = (__half2*)&r;
    hp[0] = __floats2half2_rn(f[0], f[1]);
    hp[1] = __floats2half2_rn(f[2], f[3]);
    hp[2] = __floats2half2_rn(f[4], f[5]);
    hp[3] = __floats2half2_rn(f[6], f[7]);
    return r;
}

// fused: x2 = lk01(bn(bnin_fp16)) + res(fp16) -> bf16 hi/lo images
// (uses precomputed g_scale/g_shift)
__global__ void k_apply_split(const __half* __restrict__ bnin, const __half* __restrict__ res,
                              uint4* __restrict__ ih, uint4* __restrict__ il,
                              int M, int ntiles)
{
    int task = blockIdx.x * blockDim.x + threadIdx.x;
    int total = ntiles * 128 * 32;
    if (task >= total) return;
    int r = task >> 5, k0 = (task & 31) * 8;
    float v[8];
    if (r < M) {
        float cv[8], rv[8];
        unpack8(*(const uint4*)(bnin + (size_t)r * 256 + k0), cv);
        unpack8(*(const uint4*)(res  + (size_t)r * 256 + k0), rv);
        const float4* scp = (const float4*)(g_scale + k0);
        const float4* shp = (const float4*)(g_shift + k0);
        float4 s0 = scp[0], s1 = scp[1], h0 = shp[0], h1 = shp[1];
        float sc[8] = {s0.x, s0.y, s0.z, s0.w, s1.x, s1.y, s1.z, s1.w};
        float sh[8] = {h0.x, h0.y, h0.z, h0.w, h1.x, h1.y, h1.z, h1.w};
#pragma unroll
        for (int j = 0; j < 8; j++)
            v[j] = lk01(cv[j] * sc[j] + sh[j]) + rv[j];
    } else {
#pragma unroll
        for (int j = 0; j < 8; j++) v[j] = 0.f;
    }
    img_store(ih, il, r, k0, v);
}

__global__ void k_splitB(const float* __restrict__ B, uint32_t* __restrict__ ih,
                         uint32_t* __restrict__ il, int Nc, int nct)
{
    int idx = blockIdx.x * blockDim.x + threadIdx.x;
    int total = nct * 8 * 2048;
    if (idx >= total) return;
    int ctile = idx / (8 * 2048);
    int rem0 = idx % (8 * 2048);
    int chunk = rem0 >> 11;
    int rem = rem0 & 2047;
    int lane = rem & 31;
    int t2 = rem >> 5;
    int reg = t2 & 1;
    int t3 = t2 >> 1;
    int nt16 = t3 & 15;
    int kt = t3 >> 4;
    int n = ctile * 128 + nt16 * 8 + (lane >> 2);
    int k = chunk * 32 + kt * 16 + reg * 8 + (lane & 3) * 2;
    float v0 = (n < Nc) ? B[(size_t)k * Nc + n] : 0.f;
    float v1 = (n < Nc) ? B[(size_t)(k + 1) * Nc + n] : 0.f;
    uint32_t h0, l0, h1, l1;
    bsplit(v0, h0, l0);
    bsplit(v1, h1, l1);
    ih[idx] = h0 | (h1 << 16);
    il[idx] = l0 | (l1 << 16);
}

// ---------------------------------------------------------------------------
// bf16 3-term tensor GEMM from fragment images.
// ---------------------------------------------------------------------------
__device__ __forceinline__ void mma_bf16(float* c, const uint32_t* a, const uint32_t* b) {
    asm volatile(
        "mma.sync.aligned.m16n8k16.row.col.f32.bf16.bf16.f32 "
        "{%0,%1,%2,%3}, {%4,%5,%6,%7}, {%8,%9}, {%0,%1,%2,%3};"
        : "+f"(c[0]), "+f"(c[1]), "+f"(c[2]), "+f"(c[3])
        : "r"(a[0]), "r"(a[1]), "r"(a[2]), "r"(a[3]), "r"(b[0]), "r"(b[1]));
}

__global__ void __launch_bounds__(256) k_gemm_bf16(
    const uint4* __restrict__ iAh, const uint4* __restrict__ iAl,
    const uint4* __restrict__ iBh, const uint4* __restrict__ iBl,
    const float* __restrict__ bias, float* __restrict__ C,
    int M, int Nc, int half_out)
{
    extern __shared__ uint32_t smem[];
    uint32_t sbase;
    asm("{ .reg .u64 t; cvta.to.shared.u64 t, %1; cvt.u32.u64 %0, t; }"
        : "=r"(sbase) : "l"(smem));

    int tid = threadIdx.x, lane = tid & 31, warp = tid >> 5;
    int wm = warp >> 2, wn = warp & 3;
    int tile = blockIdx.y, ctile = blockIdx.x;

    float acc[4][4][4];
#pragma unroll
    for (int mt = 0; mt < 4; mt++)
#pragma unroll
        for (int nt = 0; nt < 4; nt++)
#pragma unroll
            for (int r = 0; r < 4; r++) acc[mt][nt][r] = 0.f;

    auto issue = [&](int ch, int buf) {
        const uint4* s0 = iAh + (size_t)(tile * 8 + ch) * 512;
        const uint4* s1 = iAl + (size_t)(tile * 8 + ch) * 512;
        const uint4* s2 = iBh + (size_t)(ctile * 8 + ch) * 512;
        const uint4* s3 = iBl + (size_t)(ctile * 8 + ch) * 512;
        uint32_t d = sbase + buf * 32768;
#pragma unroll
        for (int i = 0; i < 2; i++) {
            int j = tid + i * 256;
            asm volatile("cp.async.cg.shared.global [%0], [%1], 16;\n"
                         :: "r"(d + j * 16), "l"(s0 + j));
            asm volatile("cp.async.cg.shared.global [%0], [%1], 16;\n"
                         :: "r"(d + 8192 + j * 16), "l"(s1 + j));
            asm volatile("cp.async.cg.shared.global [%0], [%1], 16;\n"
                         :: "r"(d + 16384 + j * 16), "l"(s2 + j));
            asm volatile("cp.async.cg.shared.global [%0], [%1], 16;\n"
                         :: "r"(d + 24576 + j * 16), "l"(s3 + j));
        }
        asm volatile("cp.async.commit_group;\n" ::: "memory");
    };

    issue(0, 0);

    for (int ch = 0; ch < 8; ch++) {
        if (ch + 1 < 8) {
            issue(ch + 1, (ch + 1) & 1);
            asm volatile("cp.async.wait_group 1;\n" ::: "memory");
        } else {
            asm volatile("cp.async.wait_group 0;\n" ::: "memory");
        }
        __syncthreads();

        const uint32_t* Ah = smem + (ch & 1) * 8192;
        const uint32_t* Al = Ah + 2048;
        const uint32_t* Bh = Ah + 4096;
        const uint32_t* Bl = Ah + 6144;

#pragma unroll
        for (int kt = 0; kt < 2; kt++) {
            uint32_t bh[4][2], bl[4][2];
#pragma unroll
            for (int nt = 0; nt < 4; nt++) {
                int base = ((kt * 16 + wn * 4 + nt) * 2) * 32 + lane;
                bh[nt][0] = Bh[base];      bh[nt][1] = Bh[base + 32];
                bl[nt][0] = Bl[base];      bl[nt][1] = Bl[base + 32];
            }
#pragma unroll
            for (int mt = 0; mt < 4; mt++) {
                uint32_t ah[4], al[4];
                int ab = ((kt * 8 + wm * 4 + mt) * 4) * 32 + lane;
                ah[0] = Ah[ab];       ah[1] = Ah[ab + 32];
                ah[2] = Ah[ab + 64];  ah[3] = Ah[ab + 96];
                al[0] = Al[ab];       al[1] = Al[ab + 32];
                al[2] = Al[ab + 64];  al[3] = Al[ab + 96];
#pragma unroll
                for (int nt = 0; nt < 4; nt++) {
                    mma_bf16(acc[mt][nt], ah, bh[nt]);
                    mma_bf16(acc[mt][nt], al, bh[nt]);
                    mma_bf16(acc[mt][nt], ah, bl[nt]);
                }
            }
        }
        __syncthreads();
    }

    int row0 = tile * 128, col0 = ctile * 128;
    int gid = lane >> 2, tig = lane & 3;
    __half* Ch = (__half*)C;
#pragma unroll
    for (int mt = 0; mt < 4; mt++) {
#pragma unroll
        for (int nt = 0; nt < 4; nt++) {
            int col = col0 + wn * 32 + nt * 8 + tig * 2;
            if (col < Nc) {
                float b0 = bias ? bias[col] : 0.f;
                float b1 = bias ? bias[col + 1] : 0.f;
                int r1 = row0 + wm * 64 + mt * 16 + gid;
                int r2 = r1 + 8;
                if (half_out) {
                    if (r1 < M)
                        *(__half2*)(Ch + (size_t)r1 * Nc + col) =
                            __floats2half2_rn(acc[mt][nt][0] + b0, acc[mt][nt][1] + b1);
                    if (r2 < M)
                        *(__half2*)(Ch + (size_t)r2 * Nc + col) =
                            __floats2half2_rn(acc[mt][nt][2] + b0, acc[mt][nt][3] + b1);
                } else {
                    if (r1 < M) {
                        float2 o = make_float2(acc[mt][nt][0] + b0, acc[mt][nt][1] + b1);
                        *(float2*)(C + (size_t)r1 * Nc + col) = o;
                    }
                    if (r2 < M) {
                        float2 o = make_float2(acc[mt][nt][2] + b0, acc[mt][nt][3] + b1);
                        *(float2*)(C + (size_t)r2 * Nc + col) = o;
                    }
                }
            }
        }
    }
}

// ---------------------------------------------------------------------------
// SIMT SGEMM (small layer-3/4 GEMMs); optional fp16 output
// ---------------------------------------------------------------------------
__global__ void __launch_bounds__(256) k_gemm(
    const float* __restrict__ A, const float* __restrict__ B,
    const float* __restrict__ bias, float* __restrict__ C,
    int M, int K, int Nc, int half_out)
{
    __shared__ float As[8][132];
    __shared__ float Bs[8][128];
    int tid = threadIdx.x;
    int tx = tid & 15, ty = tid >> 4;
    int row0 = blockIdx.y * 128, col0 = blockIdx.x * 128;

    int arow = tid >> 1;
    int ak   = (tid & 1) * 4;
    int brow = tid >> 5;
    int bc   = (tid & 31) * 4;

    bool aok = (row0 + arow) < M;
    bool bok = (col0 + bc + 3) < Nc;

    float acc[8][8];
#pragma unroll
    for (int i = 0; i < 8; i++)
#pragma unroll
        for (int j = 0; j < 8; j++) acc[i][j] = 0.f;

    for (int k0 = 0; k0 < K; k0 += 8) {
        float4 av = make_float4(0.f, 0.f, 0.f, 0.f);
        if (aok) av = *(const float4*)(A + (size_t)(row0 + arow) * K + k0 + ak);
        As[ak + 0][arow] = av.x;
        As[ak + 1][arow] = av.y;
        As[ak + 2][arow] = av.z;
        As[ak + 3][arow] = av.w;
        float4 bv = make_float4(0.f, 0.f, 0.f, 0.f);
        if (bok) bv = *(const float4*)(B + (size_t)(k0 + brow) * Nc + col0 + bc);
        *(float4*)&Bs[brow][bc] = bv;
        __syncthreads();
#pragma unroll
        for (int k = 0; k < 8; k++) {
            float4 a0 = *(const float4*)&As[k][ty * 8];
            float4 a1 = *(const float4*)&As[k][ty * 8 + 4];
            float4 b0 = *(const float4*)&Bs[k][tx * 8];
            float4 b1 = *(const float4*)&Bs[k][tx * 8 + 4];
            float a[8] = {a0.x, a0.y, a0.z, a0.w, a1.x, a1.y, a1.z, a1.w};
            float b[8] = {b0.x, b0.y, b0.z, b0.w, b1.x, b1.y, b1.z, b1.w};
#pragma unroll
            for (int i = 0; i < 8; i++)
#pragma unroll
                for (int j = 0; j < 8; j++) acc[i][j] += a[i] * b[j];
        }
        __syncthreads();
    }

    bool cok = (col0 + tx * 8 + 7) < Nc;
    float bvv[8];
#pragma unroll
    for (int j = 0; j < 8; j++)
        bvv[j] = (bias && cok) ? bias[col0 + tx * 8 + j] : 0.f;

    if (cok) {
        __half* Ch = (__half*)C;
#pragma unroll
        for (int i = 0; i < 8; i++) {
            int r = row0 + ty * 8 + i;
            if (r < M) {
                float o[8];
#pragma unroll
                for (int j = 0; j < 8; j++) o[j] = acc[i][j] + bvv[j];
                if (half_out) {
                    *(uint4*)(Ch + (size_t)r * Nc + col0 + tx * 8) = pack8(o);
                } else {
                    float* cp = C + (size_t)r * Nc + col0 + tx * 8;
                    *(float4*)cp = make_float4(o[0], o[1], o[2], o[3]);
                    *(float4*)(cp + 4) = make_float4(o[4], o[5], o[6], o[7]);
                }
            }
        }
    }
}

// ---------------------------------------------------------------------------
// GCN gathers
// ---------------------------------------------------------------------------
__global__ void k_gcn_gather256h(const __half* __restrict__ h, const float* __restrict__ bias,
                                 __half* __restrict__ out, int n)
{
    int gt = blockIdx.x * blockDim.x + threadIdx.x;
    int nd = gt >> 5, lane = gt & 31;
    if (nd >= n) return;
    int f0 = lane * 8;
    float din = g_dinv[nd];
    float sw = din * din;
    float v[8];
    unpack8(*(const uint4*)(h + (size_t)nd * 256 + f0), v);
    const float4* bp = (const float4*)(bias + f0);
    float4 b0 = bp[0], b1 = bp[1];
    float a[8];
    a[0] = v[0] * sw + b0.x; a[1] = v[1] * sw + b0.y;
    a[2] = v[2] * sw + b0.z; a[3] = v[3] * sw + b0.w;
    a[4] = v[4] * sw + b1.x; a[5] = v[5] * sw + b1.y;
    a[6] = v[6] * sw + b1.z; a[7] = v[7] * sw + b1.w;
    int e = g_rowptr[nd], end = g_rowptr[nd + 1];
    for (; e < end; e++) {
        int s = g_csr[e];
        float wg = g_dinv[s] * din;
        float u[8];
        unpack8(*(const uint4*)(h + (size_t)s * 256 + f0), u);
#pragma unroll
        for (int j = 0; j < 8; j++) a[j] += wg * u[j];
    }
    *(uint4*)(out + (size_t)nd * 256 + f0) = pack8(a);
}

// fp16-input gather for C in {16,64}, fp32 output
template <int C>
__global__ void k_gcn_gather_h(const __half* __restrict__ h, const float* __restrict__ bias,
                               float* __restrict__ out, int n)
{
    const int G = C / 4;
    int gt = blockIdx.x * blockDim.x + threadIdx.x;
    int nd = gt / G, sub = gt % G;
    if (nd >= n) return;
    int f0 = sub * 4;
    float din = g_dinv[nd];
    float sw = din * din;
    uint2 raw = *(const uint2*)(h + (size_t)nd * C + f0);
    __half2* hp = (__half2*)&raw;
    float2 v0 = __half22float2(hp[0]);
    float2 v1 = __half22float2(hp[1]);
    float4 b = *(const float4*)(bias + f0);
    float4 a;
    a.x = v0.x * sw + b.x; a.y = v0.y * sw + b.y;
    a.z = v1.x * sw + b.z; a.w = v1.y * sw + b.w;
    int e = g_rowptr[nd], end = g_rowptr[nd + 1];
    for (; e < end; e++) {
        int s = g_csr[e];
        float wg = g_dinv[s] * din;
        uint2 ur = *(const uint2*)(h + (size_t)s * C + f0);
        __half2* up = (__half2*)&ur;
        float2 u0 = __half22float2(up[0]);
        float2 u1 = __half22float2(up[1]);
        a.x += wg * u0.x; a.y += wg * u0.y; a.z += wg * u1.x; a.w += wg * u1.y;
    }
    *(float4*)(out + (size_t)nd * C + f0) = a;
}

// ---------------------------------------------------------------------------
// GAT kernels (fp16 hg input, fp16 output)
// ---------------------------------------------------------------------------
__global__ void k_al(const __half* __restrict__ hg, const float* __restrict__ a_s,
                     const float* __restrict__ a_d, int n)
{
    int gt = blockIdx.x * blockDim.x + threadIdx.x;
    int w = gt >> 5, lane = gt & 31;
    if (w >= n) return;
    float s0 = 0.f, s1 = 0.f, s2 = 0.f, s3 = 0.f;
    float d0 = 0.f, d1 = 0.f, d2 = 0.f, d3 = 0.f;
#pragma unroll
    for (int j = 0; j < 2; j++) {
        int f = lane * 4 + j * 128;
        uint2 raw = *(const uint2*)(hg + (size_t)w * 256 + f);
        __half2* hp = (__half2*)&raw;
        float2 p0 = __half22float2(hp[0]);
        float2 p1 = __half22float2(hp[1]);
        float4 v = make_float4(p0.x, p0.y, p1.x, p1.y);
        float4 as = *(const float4*)(a_s + f);
        float4 ad = *(const float4*)(a_d + f);
        float ps = v.x * as.x + v.y * as.y + v.z * as.z + v.w * as.w;
        float pd = v.x * ad.x + v.y * ad.y + v.z * ad.z + v.w * ad.w;
        bool hi = (lane & 16) != 0;
        if (j == 0) { if (hi) { s1 += ps; d1 += pd; } else { s0 += ps; d0 += pd; } }
        else        { if (hi) { s3 += ps; d3 += pd; } else { s2 += ps; d2 += pd; } }
    }
#pragma unroll
    for (int off = 16; off >= 1; off >>= 1) {
        s0 += __shfl_xor_sync(0xffffffffu, s0, off);
        s1 += __shfl_xor_sync(0xffffffffu, s1, off);
        s2 += __shfl_xor_sync(0xffffffffu, s2, off);
        s3 += __shfl_xor_sync(0xffffffffu, s3, off);
        d0 += __shfl_xor_sync(0xffffffffu, d0, off);
        d1 += __shfl_xor_sync(0xffffffffu, d1, off);
        d2 += __shfl_xor_sync(0xffffffffu, d2, off);
        d3 += __shfl_xor_sync(0xffffffffu, d3, off);
    }
    if (lane == 0) {
        *(float4*)(g_als + 4 * (size_t)w) = make_float4(s0, s1, s2, s3);
        *(float4*)(g_ald + 4 * (size_t)w) = make_float4(d0, d1, d2, d3);
    }
}

__global__ void k_gat(const __half* __restrict__ hg, const float* __restrict__ bg,
                      __half* __restrict__ out, int n)
{
    int gt = blockIdx.x * blockDim.x + threadIdx.x;
    int w = gt >> 5, lane = gt & 31;
    if (w >= n) return;
    float4 ad = *(const float4*)(g_ald + 4 * (size_t)w);
    float4 sf = *(const float4*)(g_als + 4 * (size_t)w);
    float e0 = lk2(sf.x + ad.x), e1 = lk2(sf.y + ad.y);
    float e2 = lk2(sf.z + ad.z), e3 = lk2(sf.w + ad.w);
    float m0 = e0, m1 = e1, m2 = e2, m3 = e3;
    int beg = g_rowptr[w], end = g_rowptr[w + 1];
    for (int e = beg; e < end; e++) {
        int s = g_csr[e];
        float4 a = *(const float4*)(g_als + 4 * (size_t)s);
        m0 = fmaxf(m0, lk2(a.x + ad.x));
        m1 = fmaxf(m1, lk2(a.y + ad.y));
        m2 = fmaxf(m2, lk2(a.z + ad.z));
        m3 = fmaxf(m3, lk2(a.w + ad.w));
    }
    float den0 = __expf(e0 - m0), den1 = __expf(e1 - m1);
    float den2 = __expf(e2 - m2), den3 = __expf(e3 - m3);
    int f0 = lane * 8;
    int head = lane >> 3;
    float wself = head == 0 ? den0 : head == 1 ? den1 : head == 2 ? den2 : den3;
    float v[8];
    unpack8(*(const uint4*)(hg + (size_t)w * 256 + f0), v);
    float a0 = wself * v[0], a1 = wself * v[1], a2 = wself * v[2], a3 = wself * v[3];
    float a4 = wself * v[4], a5 = wself * v[5], a6 = wself * v[6], a7 = wself * v[7];
    for (int e = beg; e < end; e++) {
        int s = g_csr[e];
        float4 a = *(const float4*)(g_als + 4 * (size_t)s);
        float w0 = __expf(lk2(a.x + ad.x) - m0);
        float w1 = __expf(lk2(a.y + ad.y) - m1);
        float w2 = __expf(lk2(a.z + ad.z) - m2);
        float w3 = __expf(lk2(a.w + ad.w) - m3);
        den0 += w0; den1 += w1; den2 += w2; den3 += w3;
        float ws = head == 0 ? w0 : head == 1 ? w1 : head == 2 ? w2 : w3;
        float u[8];
        unpack8(*(const uint4*)(hg + (size_t)s * 256 + f0), u);
        a0 += ws * u[0]; a1 += ws * u[1]; a2 += ws * u[2]; a3 += ws * u[3];
        a4 += ws * u[4]; a5 += ws * u[5]; a6 += ws * u[6]; a7 += ws * u[7];
    }
    float dsel = head == 0 ? den0 : head == 1 ? den1 : head == 2 ? den2 : den3;
    float sc = 0.25f / dsel;
    a0 *= sc; a1 *= sc; a2 *= sc; a3 *= sc;
    a4 *= sc; a5 *= sc; a6 *= sc; a7 *= sc;
    a0 += __shfl_xor_sync(0xffffffffu, a0, 8);  a0 += __shfl_xor_sync(0xffffffffu, a0, 16);
    a1 += __shfl_xor_sync(0xffffffffu, a1, 8);  a1 += __shfl_xor_sync(0xffffffffu, a1, 16);
    a2 += __shfl_xor_sync(0xffffffffu, a2, 8);  a2 += __shfl_xor_sync(0xffffffffu, a2, 16);
    a3 += __shfl_xor_sync(0xffffffffu, a3, 8);  a3 += __shfl_xor_sync(0xffffffffu, a3, 16);
    a4 += __shfl_xor_sync(0xffffffffu, a4, 8);  a4 += __shfl_xor_sync(0xffffffffu, a4, 16);
    a5 += __shfl_xor_sync(0xffffffffu, a5, 8);  a5 += __shfl_xor_sync(0xffffffffu, a5, 16);
    a6 += __shfl_xor_sync(0xffffffffu, a6, 8);  a6 += __shfl_xor_sync(0xffffffffu, a6, 16);
    a7 += __shfl_xor_sync(0xffffffffu, a7, 8);  a7 += __shfl_xor_sync(0xffffffffu, a7, 16);
    if (lane < 8) {
        const float4* bp = (const float4*)(bg + lane * 8);
        float4 b0 = bp[0], b1 = bp[1];
        float o[8] = {a0 + b0.x, a1 + b0.y, a2 + b0.z, a3 + b0.w,
                      a4 + b1.x, a5 + b1.y, a6 + b1.z, a7 + b1.w};
        *(uint4*)(out + (size_t)w * 64 + lane * 8) = pack8(o);
    }
}

// ---------------------------------------------------------------------------
// BatchNorm: stats / finalize / apply
// ---------------------------------------------------------------------------
template <int C>
__global__ void k_bnstats_h(const __half* __restrict__ x, float* __restrict__ gsum,
                            float* __restrict__ gsq, int n)
{
    __shared__ float ss[256], qq[256];
    int tid = threadIdx.x;
    const int R = 256 / C;
    int c = tid % C, r0 = tid / C;
    float s = 0.f, q = 0.f;
    for (int r = blockIdx.x * R + r0; r < n; r += gridDim.x * R) {
        float v = __half2float(x[(size_t)r * C + c]);
        s += v; q += v * v;
    }
    ss[tid] = s; qq[tid] = q;
    __syncthreads();
#pragma unroll
    for (int off = 128; off >= C; off >>= 1) {
        if (tid < off) { ss[tid] += ss[tid + off]; qq[tid] += qq[tid + off]; }
        __syncthreads();
    }
    if (tid < C) {
        atomicAdd(&gsum[tid], ss[tid]);
        atomicAdd(&gsq[tid],  qq[tid]);
    }
}

template <int C>
__global__ void k_bnstats(const float* __restrict__ x, float* __restrict__ gsum,
                          float* __restrict__ gsq, int n)
{
    __shared__ float ss[256], qq[256];
    int tid = threadIdx.x;
    const int R = 256 / C;
    int c = tid % C, r0 = tid / C;
    float s = 0.f, q = 0.f;
    for (int r = blockIdx.x * R + r0; r < n; r += gridDim.x * R) {
        float v = x[(size_t)r * C + c];
        s += v; q += v * v;
    }
    ss[tid] = s; qq[tid] = q;
    __syncthreads();
#pragma unroll
    for (int off = 128; off >= C; off >>= 1) {
        if (tid < off) { ss[tid] += ss[tid + off]; qq[tid] += qq[tid + off]; }
        __syncthreads();
    }
    if (tid < C) {
        atomicAdd(&gsum[tid], ss[tid]);
        atomicAdd(&gsq[tid],  qq[tid]);
    }
}

template <int C>
__global__ void k_bnfin(const float* __restrict__ gsum, const float* __restrict__ gsq,
                        const float* __restrict__ g, const float* __restrict__ be, int n)
{
    int c = threadIdx.x;
    if (c >= C) return;
    float inv = 1.0f / (float)n;
    float mu = gsum[c] * inv;
    float var = gsq[c] * inv - mu * mu;
    float sc = g[c] * rsqrtf(var + 1e-5f);
    g_scale[c] = sc;
    g_shift[c] = be[c] - mu * sc;
}

template <int C>
__global__ void k_apply(const float* __restrict__ x, const float* __restrict__ res,
                        float* __restrict__ out, int n)
{
    int i = blockIdx.x * blockDim.x + threadIdx.x;
    int total = n * (C / 4);
    if (i >= total) return;
    int c4 = i % (C / 4);
    float4 sc = *(const float4*)(g_scale + c4 * 4);
    float4 sh = *(const float4*)(g_shift + c4 * 4);
    float4 v = ((const float4*)x)[i];
    float4 r = ((const float4*)res)[i];
    float4 o;
    o.x = lk01(v.x * sc.x + sh.x) + r.x;
    o.y = lk01(v.y * sc.y + sh.y) + r.y;
    o.z = lk01(v.z * sc.z + sh.z) + r.z;
    o.w = lk01(v.w * sc.w + sh.w) + r.w;
    ((float4*)out)[i] = o;
}

// apply C=64, fp16 x + fp16 res -> fp32 (uses precomputed g_scale/g_shift)
__global__ void k_apply64hh(const __half* __restrict__ x, const __half* __restrict__ res,
                            float* __restrict__ out, int n)
{
    int i = blockIdx.x * blockDim.x + threadIdx.x;
    int total = n * 16;
    if (i >= total) return;
    int c4 = i % 16;
    float4 sc = *(const float4*)(g_scale + c4 * 4);
    float4 sh = *(const float4*)(g_shift + c4 * 4);
    uint2 xr = *(const uint2*)(x + (size_t)i * 4);
    uint2 rr = *(const uint2*)(res + (size_t)i * 4);
    __half2* xp = (__half2*)&xr;
    __half2* rp = (__half2*)&rr;
    float2 x0 = __half22float2(xp[0]);
    float2 x1 = __half22float2(xp[1]);
    float2 r0 = __half22float2(rp[0]);
    float2 r1 = __half22float2(rp[1]);
    float4 o;
    o.x = lk01(x0.x * sc.x + sh.x) + r0.x;
    o.y = lk01(x0.y * sc.y + sh.y) + r0.y;
    o.z = lk01(x1.x * sc.z + sh.z) + r1.x;
    o.w = lk01(x1.y * sc.w + sh.w) + r1.y;
    ((float4*)out)[i] = o;
}

// ---------------------------------------------------------------------------
// Launcher
// ---------------------------------------------------------------------------
extern "C" void kernel_launch(void* const* d_in, const int* in_sizes, int n_in,
                              void* d_out, int out_size)
{
    const float* x     = (const float*)d_in[0];
    const void*  ei    = d_in[1];
    const float* W1    = (const float*)d_in[2];
    const float* b1    = (const float*)d_in[3];
    const float* g1    = (const float*)d_in[4];
    const float* be1   = (const float*)d_in[5];
    const float* Wg    = (const float*)d_in[6];
    const float* a_src = (const float*)d_in[7];
    const float* a_dst = (const float*)d_in[8];
    const float* bg    = (const float*)d_in[9];
    const float* g2    = (const float*)d_in[10];
    const float* be2   = (const float*)d_in[11];
    const float* W3    = (const float*)d_in[12];
    const float* b3    = (const float*)d_in[13];
    const float* g3    = (const float*)d_in[14];
    const float* be3   = (const float*)d_in[15];
    const float* W4    = (const float*)d_in[16];
    const float* b4    = (const float*)d_in[17];
    const float* r1W   = (const float*)d_in[18];
    const float* r1b   = (const float*)d_in[19];
    const float* r2W   = (const float*)d_in[20];
    const float* r2b   = (const float*)d_in[21];
    const float* r3W   = (const float*)d_in[22];
    const float* r3b   = (const float*)d_in[23];
    const float* pW    = (const float*)d_in[24];
    const float* pb    = (const float*)d_in[25];

    int n = in_sizes[0] / 256;
    int E = in_sizes[1] / 2;
    if (E > EE) E = EE;
    int ntiles = (n + 127) / 128;
    if (ntiles > NTILES_MAX) ntiles = NTILES_MAX;

    float *pA, *pB, *pC, *p64A, *p64B, *p64C, *p16A, *p16B, *p16C;
    float *ps1, *pq1, *ps2, *pq2, *ps3, *pq3;
    uint4 *iAh, *iAl, *iW1h, *iW1l, *iR1h, *iR1l, *iWgh, *iWgl, *iR2h, *iR2l;
    cudaGetSymbolAddress((void**)&pA,   g_bufA);
    cudaGetSymbolAddress((void**)&pB,   g_bufB);
    cudaGetSymbolAddress((void**)&pC,   g_bufC);
    cudaGetSymbolAddress((void**)&p64A, g_b64A);
    cudaGetSymbolAddress((void**)&p64B, g_b64B);
    cudaGetSymbolAddress((void**)&p64C, g_b64C);
    cudaGetSymbolAddress((void**)&p16A, g_b16A);
    cudaGetSymbolAddress((void**)&p16B, g_b16B);
    cudaGetSymbolAddress((void**)&p16C, g_b16C);
    cudaGetSymbolAddress((void**)&ps1, g_s1);
    cudaGetSymbolAddress((void**)&pq1, g_q1);
    cudaGetSymbolAddress((void**)&ps2, g_s2);
    cudaGetSymbolAddress((void**)&pq2, g_q2);
    cudaGetSymbolAddress((void**)&ps3, g_s3);
    cudaGetSymbolAddress((void**)&pq3, g_q3);
    cudaGetSymbolAddress((void**)&iAh,  g_iAh);
    cudaGetSymbolAddress((void**)&iAl,  g_iAl);
    cudaGetSymbolAddress((void**)&iW1h, g_iW1h);
    cudaGetSymbolAddress((void**)&iW1l, g_iW1l);
    cudaGetSymbolAddress((void**)&iR1h, g_iR1h);
    cudaGetSymbolAddress((void**)&iR1l, g_iR1l);
    cudaGetSymbolAddress((void**)&iWgh, g_iWgh);
    cudaGetSymbolAddress((void**)&iWgl, g_iWgl);
    cudaGetSymbolAddress((void**)&iR2h, g_iR2h);
    cudaGetSymbolAddress((void**)&iR2l, g_iR2l);

    float* outp = (float*)d_out;
    const __half* pAh = (const __half*)pA;
    const __half* pBh = (const __half*)pB;
    __half* pCh = (__half*)pC;
    __half* p64Ah = (__half*)p64A;
    const __half* p64Bh = (const __half*)p64B;
    const __half* p16Ah = (const __half*)p16A;

    cudaFuncSetAttribute(k_gemm_bf16, cudaFuncAttributeMaxDynamicSharedMemorySize, 65536);

    int nb = (n + 255) / 256;
    int splitA_blocks = (ntiles * 128 * 32 + 255) / 256;
    dim3 gt256(2, ntiles);
    dim3 gt64 (1, ntiles);
    dim3 gmed (1, ntiles);

    // --- dense front ---
    k_splitB<<<128, 256>>>(W1,  (uint32_t*)iW1h, (uint32_t*)iW1l, 256, 2);
    k_splitB<<<128, 256>>>(r1W, (uint32_t*)iR1h, (uint32_t*)iR1l, 256, 2);
    k_splitB<<<128, 256>>>(Wg,  (uint32_t*)iWgh, (uint32_t*)iWgl, 256, 2);
    k_splitB<<<64,  256>>>(r2W, (uint32_t*)iR2h, (uint32_t*)iR2l, 64, 1);
    k_splitA<<<splitA_blocks, 256>>>(x, iAh, iAl, n, ntiles);
    k_gemm_bf16<<<gt256, 256, 65536>>>(iAh, iAl, iW1h, iW1l, nullptr, pA, n, 256, 1);  // fp16 h1
    k_gemm_bf16<<<gt256, 256, 65536>>>(iAh, iAl, iR1h, iR1l, r1b, pB, n, 256, 1);      // fp16 r1

    // --- graph preprocessing (zero includes dtype detect) ---
    k_zero  <<<nb, 256>>>(n, (const int*)ei, E);
    k_count <<<(E + 255) / 256, 256>>>(ei, E, n);
    k_psum  <<<nb, 256>>>(n);
    k_bscan <<<1, 256>>>(nb);
    k_rowptr<<<nb, 256>>>(n);
    k_fill  <<<(E + 255) / 256, 256>>>(ei, E, n);

    // --- layer 1: gather + BN + apply_split ---
    k_gcn_gather256h<<<(n * 32 + 255) / 256, 256>>>(pAh, b1, pCh, n);
    k_bnstats_h<256><<<512, 256>>>(pCh, ps1, pq1, n);
    k_bnfin<256><<<1, 256>>>(ps1, pq1, g1, be1, n);
    k_apply_split<<<splitA_blocks, 256>>>(pCh, pBh, iAh, iAl, n, ntiles);  // -> x2 images

    // --- layer 2: GAT(256->64) + BN + leaky + residual ---
    k_gemm_bf16<<<gt256, 256, 65536>>>(iAh, iAl, iWgh, iWgl, nullptr, pA, n, 256, 1);  // fp16 hg
    k_gemm_bf16<<<gt64, 256, 65536>>>(iAh, iAl, iR2h, iR2l, r2b, p64B, n, 64, 1);      // fp16 r2
    k_al <<<(n * 32 + 255) / 256, 256>>>(pAh, a_src, a_dst, n);
    k_gat<<<(n * 32 + 255) / 256, 256>>>(pAh, bg, p64Ah, n);
    k_bnstats_h<64><<<512, 256>>>(p64Ah, ps2, pq2, n);
    k_bnfin<64><<<1, 64>>>(ps2, pq2, g2, be2, n);
    k_apply64hh<<<(n * 16 + 255) / 256, 256>>>(p64Ah, p64Bh, p64C, n);  // x3 fp32

    // --- layer 3: GCN(64->16) + BN + leaky + residual ---
    k_gemm<<<gmed, 256>>>(p64C, W3, nullptr, p16A, n, 64, 16, 1);                      // fp16 h3
    k_gcn_gather_h<16><<<(n * 4 + 255) / 256, 256>>>(p16Ah, b3, p16B, n);
    k_gemm<<<gmed, 256>>>(p64C, r3W, r3b, p16C, n, 64, 16, 0);
    k_bnstats<16><<<512, 256>>>(p16B, ps3, pq3, n);
    k_bnfin<16><<<1, 16>>>(ps3, pq3, g3, be3, n);
    k_apply<16><<<(n * 4 + 255) / 256, 256>>>(p16B, p16C, p16A, n);   // x4 fp32

    // --- layer 4: GCN(16->64) + final projection ---
    k_gemm<<<gmed, 256>>>(p16A, W4, nullptr, p64A, n, 16, 64, 1);                      // fp16 h4
    k_gcn_gather_h<64><<<(n * 16 + 255) / 256, 256>>>(p64Ah, b4, p64B, n);
    k_gemm<<<gmed, 256>>>(p64B, pW, pb, outp, n, 64, 64, 0);
}